// round 3
// baseline (speedup 1.0000x reference)
#include <cuda_runtime.h>
#include <cuda_fp16.h>
#include <cstdint>

// ===========================================================================
// QLinear: y[8192,4096] = x[8192,4096] @ w^T + bias,  w = sum_k kron(a_k,s_k)
//
// ptxas on this harness targets plain sm_103 (no 'a'): tcgen05/TMEM/TMA-
// multicast unavailable. sm_80-base tensor-core path:
//   k1: x fp32 -> fp16 scratch
//   k2: w = sum_k a[k] kron s[k], scaled by 256, fp16 scratch
//   k3: mma.sync m16n8k16 GEMM, 128x128x64 tiles, 4-stage cp.async pipeline,
//       swizzled smem + ldmatrix, epilogue *(1/256) + bias
// R3 fixes vs R2: exact tail wait-group invariant (empty commits), no static
// guard in kernel_launch.
// ===========================================================================

static constexpr int TOKENS = 8192;
static constexpr int IN_F   = 4096;
static constexpr int OUT_F  = 4096;

static constexpr int BM = 128;
static constexpr int BN = 128;
static constexpr int BK = 64;                       // halfs; 128B rows
static constexpr int STAGES = 4;
static constexpr int KITERS = IN_F / BK;            // 64

static constexpr int TILE_BYTES  = BM * BK * 2;     // 16 KB (A or B)
static constexpr int STAGE_BYTES = 2 * TILE_BYTES;  // 32 KB
static constexpr int SMEM_TOTAL  = STAGES * STAGE_BYTES;  // 128 KB

static constexpr float W_SCALE     = 256.0f;
static constexpr float INV_W_SCALE = 1.0f / 256.0f;

__device__ __half g_xh[(size_t)TOKENS * IN_F];   // 64 MB scratch
__device__ __half g_wh[(size_t)OUT_F * IN_F];    // 32 MB scratch

#define DI static __device__ __forceinline__

DI uint32_t smem_u32(const void* p) {
    uint32_t a;
    asm("{ .reg .u64 t; cvta.to.shared.u64 t, %1; cvt.u32.u64 %0, t; }"
        : "=r"(a) : "l"(p));
    return a;
}

#define CP_ASYNC_16(dst, src) \
    asm volatile("cp.async.cg.shared.global [%0], [%1], 16;" \
        :: "r"(dst), "l"(src) : "memory")

#define CP_ASYNC_COMMIT() asm volatile("cp.async.commit_group;" ::: "memory")
#define CP_ASYNC_WAIT2()  asm volatile("cp.async.wait_group 2;" ::: "memory")

#define LDSM_X4(R0, R1, R2, R3, addr) \
    asm volatile("ldmatrix.sync.aligned.m8n8.x4.shared.b16 {%0,%1,%2,%3}, [%4];" \
        : "=r"(R0), "=r"(R1), "=r"(R2), "=r"(R3) : "r"(addr))

#define MMA16816(C, A0, A1, A2, A3, B0, B1) \
    asm volatile("mma.sync.aligned.m16n8k16.row.col.f32.f16.f16.f32 " \
        "{%0,%1,%2,%3}, {%4,%5,%6,%7}, {%8,%9}, {%0,%1,%2,%3};" \
        : "+f"((C)[0]), "+f"((C)[1]), "+f"((C)[2]), "+f"((C)[3]) \
        : "r"(A0), "r"(A1), "r"(A2), "r"(A3), "r"(B0), "r"(B1))

// ------------------------------ prep kernels ------------------------------

// x fp32 -> fp16, 4 elems / thread
__global__ void conv_x_kernel(const float* __restrict__ x) {
    size_t t = (size_t)blockIdx.x * blockDim.x + threadIdx.x;
    float4 v = reinterpret_cast<const float4*>(x)[t];
    __half2* o = reinterpret_cast<__half2*>(g_xh);
    o[2 * t + 0] = __floats2half2_rn(v.x, v.y);
    o[2 * t + 1] = __floats2half2_rn(v.z, v.w);
}

// w[i*1024+p, j*1024+q] = sum_k a[k,i,j]*s[k,p,q]; thread = (j,p,q), i looped
__global__ void build_w_kernel(const float* __restrict__ a,
                               const float* __restrict__ s) {
    uint32_t t = blockIdx.x * blockDim.x + threadIdx.x;   // 4M threads
    uint32_t q = t & 1023u;
    uint32_t p = (t >> 10) & 1023u;
    uint32_t j = t >> 20;

    float s0 = s[0u * 1048576u + p * 1024u + q];
    float s1 = s[1u * 1048576u + p * 1024u + q];
    float s2 = s[2u * 1048576u + p * 1024u + q];
    float s3 = s[3u * 1048576u + p * 1024u + q];

#pragma unroll
    for (int i = 0; i < 4; i++) {
        float w = __ldg(&a[0 * 16 + i * 4 + j]) * s0
                + __ldg(&a[1 * 16 + i * 4 + j]) * s1
                + __ldg(&a[2 * 16 + i * 4 + j]) * s2
                + __ldg(&a[3 * 16 + i * 4 + j]) * s3;
        g_wh[(size_t)(i * 1024 + p) * IN_F + j * 1024 + q] =
            __float2half_rn(w * W_SCALE);
    }
}

// ------------------------------ GEMM kernel -------------------------------
// Warp grid 4x2: warp (wm in 0..3, wn in 0..1) computes a 32x64 tile.
// Per warp: 2 m16 tiles x 8 n8 tiles, k in steps of 16.
// SMEM: per stage, A[128][64] then B[128][64]; 128B rows, 16B chunk c stored
// at (c ^ (row & 7)) -> conflict-free ldmatrix + cp.async.

__global__ __launch_bounds__(256, 1)
void gemm_kernel(const float* __restrict__ bias, float* __restrict__ out) {
    extern __shared__ char smem[];
    const uint32_t sbase = smem_u32(smem);

    const int tid  = threadIdx.x;
    const int lane = tid & 31;
    const int wid  = tid >> 5;
    const int wm   = wid & 3;     // warp row
    const int wn   = wid >> 2;    // warp col
    const int g    = lane >> 3;   // ldmatrix 8x8 sub-matrix id
    const int r    = lane & 7;    // row within sub-matrix

    const int Mtile = blockIdx.x;
    const int Ntile = blockIdx.y;

    const __half* gA = g_xh + (size_t)(Mtile * BM) * IN_F;
    const __half* gB = g_wh + (size_t)(Ntile * BN) * IN_F;

    // --- cp.async issue for one k-tile into stage s (A and B) ---
    auto issue = [&](int kt, int s) {
        const uint32_t base = sbase + s * STAGE_BYTES;
#pragma unroll
        for (int it = 0; it < 4; it++) {
            int idx = tid + it * 256;          // 0..1023
            int m = idx >> 3;                  // row 0..127
            int c = idx & 7;                   // 16B chunk 0..7
            uint32_t off = m * 128 + ((c ^ (m & 7)) << 4);
            const __half* srcA = gA + (size_t)m * IN_F + kt * BK + c * 8;
            const __half* srcB = gB + (size_t)m * IN_F + kt * BK + c * 8;
            CP_ASYNC_16(base + off, srcA);
            CP_ASYNC_16(base + TILE_BYTES + off, srcB);
        }
        CP_ASYNC_COMMIT();
    };

    // --- per-lane ldmatrix row bases ---
    int rowA[2];
    const int cpA = g >> 1;
#pragma unroll
    for (int mi = 0; mi < 2; mi++)
        rowA[mi] = wm * 32 + mi * 16 + (g & 1) * 8 + r;
    int rowB[4];
    const int cpB = g & 1;
#pragma unroll
    for (int tp = 0; tp < 4; tp++)
        rowB[tp] = wn * 64 + tp * 16 + ((g >> 1) & 1) * 8 + r;

    float acc[2][8][4];
#pragma unroll
    for (int mi = 0; mi < 2; mi++)
#pragma unroll
        for (int ni = 0; ni < 8; ni++)
#pragma unroll
            for (int e = 0; e < 4; e++) acc[mi][ni][e] = 0.0f;

    // --- prologue: fill STAGES-1 stages ---
    issue(0, 0);
    issue(1, 1);
    issue(2, 2);

    // --- mainloop ---
    // Invariant: exactly one commit_group per iteration (real or empty), so
    // before WAIT2 at iteration kt there are 3 pending groups and wait_group 2
    // retires group kt exactly.
    for (int kt = 0; kt < KITERS; kt++) {
        const int s = kt & (STAGES - 1);
        CP_ASYNC_WAIT2();
        __syncthreads();
        if (kt + 3 < KITERS) {
            issue(kt + 3, (kt + 3) & (STAGES - 1));
        } else {
            CP_ASYNC_COMMIT();   // empty group keeps the pending-count exact
        }

        const uint32_t As = sbase + s * STAGE_BYTES;
        const uint32_t Bs = As + TILE_BYTES;

#pragma unroll
        for (int ks = 0; ks < 4; ks++) {
            const uint32_t chA = (uint32_t)(((2 * ks + cpA) ^ r) << 4);
            const uint32_t chB = (uint32_t)(((2 * ks + cpB) ^ r) << 4);

            uint32_t a[2][4];
#pragma unroll
            for (int mi = 0; mi < 2; mi++)
                LDSM_X4(a[mi][0], a[mi][1], a[mi][2], a[mi][3],
                        As + rowA[mi] * 128 + chA);

            uint32_t b[4][4];
#pragma unroll
            for (int tp = 0; tp < 4; tp++)
                LDSM_X4(b[tp][0], b[tp][1], b[tp][2], b[tp][3],
                        Bs + rowB[tp] * 128 + chB);

#pragma unroll
            for (int mi = 0; mi < 2; mi++)
#pragma unroll
                for (int tp = 0; tp < 4; tp++) {
                    MMA16816(acc[mi][tp * 2 + 0],
                             a[mi][0], a[mi][1], a[mi][2], a[mi][3],
                             b[tp][0], b[tp][1]);
                    MMA16816(acc[mi][tp * 2 + 1],
                             a[mi][0], a[mi][1], a[mi][2], a[mi][3],
                             b[tp][2], b[tp][3]);
                }
        }
        __syncthreads();
    }

    // --- epilogue: *(1/256) + bias, fp32 out ---
    const int q  = lane >> 2;        // 0..7
    const int cc = (lane & 3) * 2;

    float2 bv[8];
#pragma unroll
    for (int ni = 0; ni < 8; ni++) {
        int n = Ntile * BN + wn * 64 + ni * 8 + cc;
        bv[ni] = *reinterpret_cast<const float2*>(bias + n);
    }

#pragma unroll
    for (int mi = 0; mi < 2; mi++) {
        int m0 = Mtile * BM + wm * 32 + mi * 16 + q;
#pragma unroll
        for (int ni = 0; ni < 8; ni++) {
            int n = Ntile * BN + wn * 64 + ni * 8 + cc;
            float2 v0, v1;
            v0.x = acc[mi][ni][0] * INV_W_SCALE + bv[ni].x;
            v0.y = acc[mi][ni][1] * INV_W_SCALE + bv[ni].y;
            v1.x = acc[mi][ni][2] * INV_W_SCALE + bv[ni].x;
            v1.y = acc[mi][ni][3] * INV_W_SCALE + bv[ni].y;
            *reinterpret_cast<float2*>(out + (size_t)m0 * OUT_F + n) = v0;
            *reinterpret_cast<float2*>(out + (size_t)(m0 + 8) * OUT_F + n) = v1;
        }
    }
}

// ------------------------------ host launch -------------------------------

extern "C" void kernel_launch(void* const* d_in, const int* in_sizes, int n_in,
                              void* d_out, int out_size) {
    const float* x    = (const float*)d_in[0];
    const float* a    = (const float*)d_in[1];
    const float* s    = (const float*)d_in[2];
    const float* bias = (const float*)d_in[3];
    float* out = (float*)d_out;

    conv_x_kernel<<<(int)((size_t)TOKENS * IN_F / 4 / 256), 256>>>(x);
    build_w_kernel<<<(4u * 1024u * 1024u) / 256u, 256>>>(a, s);

    cudaFuncSetAttribute(gemm_kernel,
                         cudaFuncAttributeMaxDynamicSharedMemorySize,
                         SMEM_TOTAL);
    gemm_kernel<<<dim3(TOKENS / BM, OUT_F / BN, 1), 256, SMEM_TOTAL>>>(bias, out);
}

// round 4
// speedup vs baseline: 1.1686x; 1.1686x over previous
#include <cuda_runtime.h>
#include <cuda_fp16.h>
#include <cstdint>

// ===========================================================================
// QLinear: y[8192,4096] = x[8192,4096] @ w^T + bias,  w = sum_k kron(a_k,s_k)
//
// R4: GEMM was smem-crossbar (ldmatrix) bound at 32x64 warp tiles
// (192KB smem reads per CTA-ktile = 1536 cyc > 1024 cyc HMMA floor).
// New config: BM=128 BN=256 BK=64, 8 warps (2x4), warp tile 64x64
// -> 128KB smem reads/ktile = 1024 cyc, balanced with HMMA floor.
// 3-stage cp.async pipeline (144KB smem).
// ===========================================================================

static constexpr int TOKENS = 8192;
static constexpr int IN_F   = 4096;
static constexpr int OUT_F  = 4096;

static constexpr int BM = 128;
static constexpr int BN = 256;
static constexpr int BK = 64;                        // halfs; 128B rows
static constexpr int STAGES = 3;
static constexpr int KITERS = IN_F / BK;             // 64

static constexpr int A_BYTES = BM * BK * 2;          // 16 KB
static constexpr int B_BYTES = BN * BK * 2;          // 32 KB
static constexpr int STAGE_BYTES = A_BYTES + B_BYTES;      // 48 KB
static constexpr int SMEM_TOTAL  = STAGES * STAGE_BYTES;   // 144 KB

static constexpr float W_SCALE     = 256.0f;
static constexpr float INV_W_SCALE = 1.0f / 256.0f;

__device__ __half g_xh[(size_t)TOKENS * IN_F];   // 64 MB scratch
__device__ __half g_wh[(size_t)OUT_F * IN_F];    // 32 MB scratch

#define DI static __device__ __forceinline__

DI uint32_t smem_u32(const void* p) {
    uint32_t a;
    asm("{ .reg .u64 t; cvta.to.shared.u64 t, %1; cvt.u32.u64 %0, t; }"
        : "=r"(a) : "l"(p));
    return a;
}

#define CP_ASYNC_16(dst, src) \
    asm volatile("cp.async.cg.shared.global [%0], [%1], 16;" \
        :: "r"(dst), "l"(src) : "memory")

#define CP_ASYNC_COMMIT() asm volatile("cp.async.commit_group;" ::: "memory")
#define CP_ASYNC_WAIT1()  asm volatile("cp.async.wait_group 1;" ::: "memory")

#define LDSM_X4(R0, R1, R2, R3, addr) \
    asm volatile("ldmatrix.sync.aligned.m8n8.x4.shared.b16 {%0,%1,%2,%3}, [%4];" \
        : "=r"(R0), "=r"(R1), "=r"(R2), "=r"(R3) : "r"(addr))

#define MMA16816(C, A0, A1, A2, A3, B0, B1) \
    asm volatile("mma.sync.aligned.m16n8k16.row.col.f32.f16.f16.f32 " \
        "{%0,%1,%2,%3}, {%4,%5,%6,%7}, {%8,%9}, {%0,%1,%2,%3};" \
        : "+f"((C)[0]), "+f"((C)[1]), "+f"((C)[2]), "+f"((C)[3]) \
        : "r"(A0), "r"(A1), "r"(A2), "r"(A3), "r"(B0), "r"(B1))

// ------------------------------ prep kernels ------------------------------

// x fp32 -> fp16, 4 elems / thread  (measured 30.7us @ 70% HBM)
__global__ void conv_x_kernel(const float* __restrict__ x) {
    size_t t = (size_t)blockIdx.x * blockDim.x + threadIdx.x;
    float4 v = reinterpret_cast<const float4*>(x)[t];
    __half2* o = reinterpret_cast<__half2*>(g_xh);
    o[2 * t + 0] = __floats2half2_rn(v.x, v.y);
    o[2 * t + 1] = __floats2half2_rn(v.z, v.w);
}

// w[i*1024+p, j*1024+q] = sum_k a[k,i,j]*s[k,p,q]; thread = (j,p,q), i looped
__global__ void build_w_kernel(const float* __restrict__ a,
                               const float* __restrict__ s) {
    uint32_t t = blockIdx.x * blockDim.x + threadIdx.x;   // 4M threads
    uint32_t q = t & 1023u;
    uint32_t p = (t >> 10) & 1023u;
    uint32_t j = t >> 20;

    float s0 = s[0u * 1048576u + p * 1024u + q];
    float s1 = s[1u * 1048576u + p * 1024u + q];
    float s2 = s[2u * 1048576u + p * 1024u + q];
    float s3 = s[3u * 1048576u + p * 1024u + q];

#pragma unroll
    for (int i = 0; i < 4; i++) {
        float w = __ldg(&a[0 * 16 + i * 4 + j]) * s0
                + __ldg(&a[1 * 16 + i * 4 + j]) * s1
                + __ldg(&a[2 * 16 + i * 4 + j]) * s2
                + __ldg(&a[3 * 16 + i * 4 + j]) * s3;
        g_wh[(size_t)(i * 1024 + p) * IN_F + j * 1024 + q] =
            __float2half_rn(w * W_SCALE);
    }
}

// ------------------------------ GEMM kernel -------------------------------
// Warp grid 2x4: warp (wm in 0..1, wn in 0..3) computes a 64x64 tile.
// Per warp per 16-wide k-step: 4 m16 A frags, 4 B ldsm (8 n8 frags), 32 MMA.
// SMEM per stage: A[128][64] then B[256][64]; 128B rows, 16B chunk c stored
// at (c ^ (row & 7)) -> conflict-free ldmatrix + cp.async.

__global__ __launch_bounds__(256, 1)
void gemm_kernel(const float* __restrict__ bias, float* __restrict__ out) {
    extern __shared__ char smem[];
    const uint32_t sbase = smem_u32(smem);

    const int tid  = threadIdx.x;
    const int lane = tid & 31;
    const int wid  = tid >> 5;
    const int wm   = wid & 1;     // warp row (2)
    const int wn   = wid >> 1;    // warp col (4)
    const int g    = lane >> 3;   // ldmatrix 8x8 sub-matrix id
    const int r    = lane & 7;    // row within sub-matrix

    const int Mtile = blockIdx.x;
    const int Ntile = blockIdx.y;

    const __half* gA = g_xh + (size_t)(Mtile * BM) * IN_F;
    const __half* gB = g_wh + (size_t)(Ntile * BN) * IN_F;

    // --- cp.async issue for one k-tile into stage s ---
    auto issue = [&](int kt, int s) {
        const uint32_t base = sbase + s * STAGE_BYTES;
        // A: 1024 16B chunks
#pragma unroll
        for (int it = 0; it < 4; it++) {
            int idx = tid + it * 256;
            int m = idx >> 3, c = idx & 7;
            uint32_t off = m * 128 + ((c ^ (m & 7)) << 4);
            CP_ASYNC_16(base + off, gA + (size_t)m * IN_F + kt * BK + c * 8);
        }
        // B: 2048 16B chunks
#pragma unroll
        for (int it = 0; it < 8; it++) {
            int idx = tid + it * 256;
            int n = idx >> 3, c = idx & 7;
            uint32_t off = n * 128 + ((c ^ (n & 7)) << 4);
            CP_ASYNC_16(base + A_BYTES + off,
                        gB + (size_t)n * IN_F + kt * BK + c * 8);
        }
        CP_ASYNC_COMMIT();
    };

    // --- per-lane ldmatrix row bases ---
    // A x4: g0:(m0+r, even k-chunk) g1:(m0+8+r, even) g2:(m0+r, odd) g3:(m0+8+r, odd)
    int rowA[4];
    const int cpA = g >> 1;
#pragma unroll
    for (int mi = 0; mi < 4; mi++)
        rowA[mi] = wm * 64 + mi * 16 + (g & 1) * 8 + r;
    // B x4: g0:(n0+r, even) g1:(n0+r, odd) g2:(n0+8+r, even) g3:(n0+8+r, odd)
    int rowB[4];
    const int cpB = g & 1;
#pragma unroll
    for (int tp = 0; tp < 4; tp++)
        rowB[tp] = wn * 64 + tp * 16 + ((g >> 1) & 1) * 8 + r;

    float acc[4][8][4];
#pragma unroll
    for (int mi = 0; mi < 4; mi++)
#pragma unroll
        for (int ni = 0; ni < 8; ni++)
#pragma unroll
            for (int e = 0; e < 4; e++) acc[mi][ni][e] = 0.0f;

    // --- prologue: fill STAGES-1 = 2 stages ---
    issue(0, 0);
    issue(1, 1);

    // --- mainloop ---
    // Invariant: one commit per iteration; before WAIT1 at iter kt there are
    // 2 pending groups, wait_group 1 retires group kt exactly.
    int s = 0, sI = 2;   // consume stage, next issue stage
    for (int kt = 0; kt < KITERS; kt++) {
        CP_ASYNC_WAIT1();
        __syncthreads();
        if (kt + 2 < KITERS) {
            issue(kt + 2, sI);
            if (++sI == STAGES) sI = 0;
        } else {
            CP_ASYNC_COMMIT();   // empty group keeps pending-count exact
        }

        const uint32_t As = sbase + s * STAGE_BYTES;
        const uint32_t Bs = As + A_BYTES;

#pragma unroll
        for (int ks = 0; ks < 4; ks++) {
            const uint32_t chA = (uint32_t)(((2 * ks + cpA) ^ r) << 4);
            const uint32_t chB = (uint32_t)(((2 * ks + cpB) ^ r) << 4);

            uint32_t a[4][4];
#pragma unroll
            for (int mi = 0; mi < 4; mi++)
                LDSM_X4(a[mi][0], a[mi][1], a[mi][2], a[mi][3],
                        As + rowA[mi] * 128 + chA);

            uint32_t b[4][4];
#pragma unroll
            for (int tp = 0; tp < 4; tp++)
                LDSM_X4(b[tp][0], b[tp][1], b[tp][2], b[tp][3],
                        Bs + rowB[tp] * 128 + chB);

#pragma unroll
            for (int mi = 0; mi < 4; mi++)
#pragma unroll
                for (int tp = 0; tp < 4; tp++) {
                    MMA16816(acc[mi][tp * 2 + 0],
                             a[mi][0], a[mi][1], a[mi][2], a[mi][3],
                             b[tp][0], b[tp][1]);
                    MMA16816(acc[mi][tp * 2 + 1],
                             a[mi][0], a[mi][1], a[mi][2], a[mi][3],
                             b[tp][2], b[tp][3]);
                }
        }
        __syncthreads();
        if (++s == STAGES) s = 0;
    }

    // --- epilogue: *(1/256) + bias, fp32 out ---
    const int q  = lane >> 2;        // 0..7
    const int cc = (lane & 3) * 2;

    float2 bv[8];
#pragma unroll
    for (int ni = 0; ni < 8; ni++) {
        int n = Ntile * BN + wn * 64 + ni * 8 + cc;
        bv[ni] = *reinterpret_cast<const float2*>(bias + n);
    }

#pragma unroll
    for (int mi = 0; mi < 4; mi++) {
        int m0 = Mtile * BM + wm * 64 + mi * 16 + q;
#pragma unroll
        for (int ni = 0; ni < 8; ni++) {
            int n = Ntile * BN + wn * 64 + ni * 8 + cc;
            float2 v0, v1;
            v0.x = acc[mi][ni][0] * INV_W_SCALE + bv[ni].x;
            v0.y = acc[mi][ni][1] * INV_W_SCALE + bv[ni].y;
            v1.x = acc[mi][ni][2] * INV_W_SCALE + bv[ni].x;
            v1.y = acc[mi][ni][3] * INV_W_SCALE + bv[ni].y;
            *reinterpret_cast<float2*>(out + (size_t)m0 * OUT_F + n) = v0;
            *reinterpret_cast<float2*>(out + (size_t)(m0 + 8) * OUT_F + n) = v1;
        }
    }
}

// ------------------------------ host launch -------------------------------

extern "C" void kernel_launch(void* const* d_in, const int* in_sizes, int n_in,
                              void* d_out, int out_size) {
    const float* x    = (const float*)d_in[0];
    const float* a    = (const float*)d_in[1];
    const float* s    = (const float*)d_in[2];
    const float* bias = (const float*)d_in[3];
    float* out = (float*)d_out;

    conv_x_kernel<<<(int)((size_t)TOKENS * IN_F / 4 / 256), 256>>>(x);
    build_w_kernel<<<(4u * 1024u * 1024u) / 256u, 256>>>(a, s);

    cudaFuncSetAttribute(gemm_kernel,
                         cudaFuncAttributeMaxDynamicSharedMemorySize,
                         SMEM_TOTAL);
    gemm_kernel<<<dim3(TOKENS / BM, OUT_F / BN, 1), 256, SMEM_TOTAL>>>(bias, out);
}

// round 5
// speedup vs baseline: 1.2766x; 1.0924x over previous
#include <cuda_runtime.h>
#include <cuda_fp16.h>
#include <cstdint>

// ===========================================================================
// QLinear: y[8192,4096] = x[8192,4096] @ w^T + bias,  w = sum_k kron(a_k,s_k)
//
// Model (R3+R4 evidence): fallback HMMA.16816.F32 rt=8 cyc/SMSP on sm_103
// => GEMM floor 2048 cyc per 64-wide ktile; R4 ran at ~2700 (76%).
// R5: cut per-ktile overhead:
//   - BK=128, 2 stages (96KB/stage, 192KB smem): half the sync boundaries
//   - fragment double-buffering across ks steps (hide LDSM latency)
// Config: BM=128 BN=256 BK=128, 8 warps (2x4), warp tile 64x64.
// ===========================================================================

static constexpr int TOKENS = 8192;
static constexpr int IN_F   = 4096;
static constexpr int OUT_F  = 4096;

static constexpr int BM = 128;
static constexpr int BN = 256;
static constexpr int BK = 128;                       // halfs; 256B rows
static constexpr int STAGES = 2;
static constexpr int KITERS = IN_F / BK;             // 32

static constexpr int ROWB = BK * 2;                  // 256 B per smem row
static constexpr int A_BYTES = BM * ROWB;            // 32 KB
static constexpr int B_BYTES = BN * ROWB;            // 64 KB
static constexpr int STAGE_BYTES = A_BYTES + B_BYTES;      // 96 KB
static constexpr int SMEM_TOTAL  = STAGES * STAGE_BYTES;   // 192 KB

static constexpr float W_SCALE     = 256.0f;
static constexpr float INV_W_SCALE = 1.0f / 256.0f;

__device__ __half g_xh[(size_t)TOKENS * IN_F];   // 64 MB scratch
__device__ __half g_wh[(size_t)OUT_F * IN_F];    // 32 MB scratch

#define DI static __device__ __forceinline__

DI uint32_t smem_u32(const void* p) {
    uint32_t a;
    asm("{ .reg .u64 t; cvta.to.shared.u64 t, %1; cvt.u32.u64 %0, t; }"
        : "=r"(a) : "l"(p));
    return a;
}

#define CP_ASYNC_16(dst, src) \
    asm volatile("cp.async.cg.shared.global [%0], [%1], 16;" \
        :: "r"(dst), "l"(src) : "memory")

#define CP_ASYNC_COMMIT() asm volatile("cp.async.commit_group;" ::: "memory")
#define CP_ASYNC_WAIT1()  asm volatile("cp.async.wait_group 1;" ::: "memory")

#define LDSM_X4(R0, R1, R2, R3, addr) \
    asm volatile("ldmatrix.sync.aligned.m8n8.x4.shared.b16 {%0,%1,%2,%3}, [%4];" \
        : "=r"(R0), "=r"(R1), "=r"(R2), "=r"(R3) : "r"(addr))

#define MMA16816(C, A0, A1, A2, A3, B0, B1) \
    asm volatile("mma.sync.aligned.m16n8k16.row.col.f32.f16.f16.f32 " \
        "{%0,%1,%2,%3}, {%4,%5,%6,%7}, {%8,%9}, {%0,%1,%2,%3};" \
        : "+f"((C)[0]), "+f"((C)[1]), "+f"((C)[2]), "+f"((C)[3]) \
        : "r"(A0), "r"(A1), "r"(A2), "r"(A3), "r"(B0), "r"(B1))

// ------------------------------ prep kernels ------------------------------

__global__ void conv_x_kernel(const float* __restrict__ x) {
    size_t t = (size_t)blockIdx.x * blockDim.x + threadIdx.x;
    float4 v = reinterpret_cast<const float4*>(x)[t];
    __half2* o = reinterpret_cast<__half2*>(g_xh);
    o[2 * t + 0] = __floats2half2_rn(v.x, v.y);
    o[2 * t + 1] = __floats2half2_rn(v.z, v.w);
}

__global__ void build_w_kernel(const float* __restrict__ a,
                               const float* __restrict__ s) {
    uint32_t t = blockIdx.x * blockDim.x + threadIdx.x;   // 4M threads
    uint32_t q = t & 1023u;
    uint32_t p = (t >> 10) & 1023u;
    uint32_t j = t >> 20;

    float s0 = s[0u * 1048576u + p * 1024u + q];
    float s1 = s[1u * 1048576u + p * 1024u + q];
    float s2 = s[2u * 1048576u + p * 1024u + q];
    float s3 = s[3u * 1048576u + p * 1024u + q];

#pragma unroll
    for (int i = 0; i < 4; i++) {
        float w = __ldg(&a[0 * 16 + i * 4 + j]) * s0
                + __ldg(&a[1 * 16 + i * 4 + j]) * s1
                + __ldg(&a[2 * 16 + i * 4 + j]) * s2
                + __ldg(&a[3 * 16 + i * 4 + j]) * s3;
        g_wh[(size_t)(i * 1024 + p) * IN_F + j * 1024 + q] =
            __float2half_rn(w * W_SCALE);
    }
}

// ------------------------------ GEMM kernel -------------------------------
// SMEM rows are 256B (16 chunks of 16B); 16B chunk c of row m stored at
// (c ^ (m & 7)) within its row -> conflict-free ldmatrix & cp.async.

__global__ __launch_bounds__(256, 1)
void gemm_kernel(const float* __restrict__ bias, float* __restrict__ out) {
    extern __shared__ char smem[];
    const uint32_t sbase = smem_u32(smem);

    const int tid  = threadIdx.x;
    const int lane = tid & 31;
    const int wid  = tid >> 5;
    const int wm   = wid & 1;     // warp row (2)
    const int wn   = wid >> 1;    // warp col (4)
    const int g    = lane >> 3;   // ldmatrix 8x8 sub-matrix id
    const int r    = lane & 7;    // row within sub-matrix

    const int Mtile = blockIdx.x;
    const int Ntile = blockIdx.y;

    const __half* gA = g_xh + (size_t)(Mtile * BM) * IN_F;
    const __half* gB = g_wh + (size_t)(Ntile * BN) * IN_F;

    // --- cp.async issue for one k-tile into stage st ---
    auto issue = [&](int kt, int st) {
        const uint32_t base = sbase + st * STAGE_BYTES;
        // A: 2048 16B chunks
#pragma unroll
        for (int it = 0; it < 8; it++) {
            int idx = tid + it * 256;
            int m = idx >> 4, c = idx & 15;
            uint32_t off = m * ROWB + ((c ^ (m & 7)) << 4);
            CP_ASYNC_16(base + off, gA + (size_t)m * IN_F + kt * BK + c * 8);
        }
        // B: 4096 16B chunks
#pragma unroll
        for (int it = 0; it < 16; it++) {
            int idx = tid + it * 256;
            int n = idx >> 4, c = idx & 15;
            uint32_t off = n * ROWB + ((c ^ (n & 7)) << 4);
            CP_ASYNC_16(base + A_BYTES + off,
                        gB + (size_t)n * IN_F + kt * BK + c * 8);
        }
        CP_ASYNC_COMMIT();
    };

    // --- per-lane ldmatrix row bases ---
    int rowA[4];
    const int cpA = g >> 1;
#pragma unroll
    for (int mi = 0; mi < 4; mi++)
        rowA[mi] = wm * 64 + mi * 16 + (g & 1) * 8 + r;
    int rowB[4];
    const int cpB = g & 1;
#pragma unroll
    for (int tp = 0; tp < 4; tp++)
        rowB[tp] = wn * 64 + tp * 16 + ((g >> 1) & 1) * 8 + r;

    // ks in 0..7 selects 32B (2-chunk) k-slice within the 256B row
    auto load_frags = [&](uint32_t As, uint32_t Bs, int ks,
                          uint32_t (&a)[4][4], uint32_t (&b)[4][4]) {
        const uint32_t chA = (uint32_t)(((2 * ks + cpA) ^ r) << 4);
        const uint32_t chB = (uint32_t)(((2 * ks + cpB) ^ r) << 4);
#pragma unroll
        for (int mi = 0; mi < 4; mi++)
            LDSM_X4(a[mi][0], a[mi][1], a[mi][2], a[mi][3],
                    As + rowA[mi] * ROWB + chA);
#pragma unroll
        for (int tp = 0; tp < 4; tp++)
            LDSM_X4(b[tp][0], b[tp][1], b[tp][2], b[tp][3],
                    Bs + rowB[tp] * ROWB + chB);
    };

    float acc[4][8][4];
#pragma unroll
    for (int mi = 0; mi < 4; mi++)
#pragma unroll
        for (int ni = 0; ni < 8; ni++)
#pragma unroll
            for (int e = 0; e < 4; e++) acc[mi][ni][e] = 0.0f;

    // --- prologue ---
    issue(0, 0);
    issue(1, 1);
    CP_ASYNC_WAIT1();     // group 0 complete (2 pending -> <=1 pending)
    __syncthreads();

    uint32_t af[2][4][4], bf[2][4][4];
    load_frags(sbase, sbase + A_BYTES, 0, af[0], bf[0]);

    // --- mainloop ---
    int s = 0;
    for (int kt = 0; kt < KITERS; kt++) {
        const uint32_t As = sbase + s * STAGE_BYTES;
        const uint32_t Bs = As + A_BYTES;

#pragma unroll
        for (int ks = 0; ks < 8; ks++) {
            const int cur = ks & 1;
            if (ks < 7) load_frags(As, Bs, ks + 1, af[cur ^ 1], bf[cur ^ 1]);
#pragma unroll
            for (int mi = 0; mi < 4; mi++)
#pragma unroll
                for (int tp = 0; tp < 4; tp++) {
                    MMA16816(acc[mi][tp * 2 + 0],
                             af[cur][mi][0], af[cur][mi][1],
                             af[cur][mi][2], af[cur][mi][3],
                             bf[cur][tp][0], bf[cur][tp][1]);
                    MMA16816(acc[mi][tp * 2 + 1],
                             af[cur][mi][0], af[cur][mi][1],
                             af[cur][mi][2], af[cur][mi][3],
                             bf[cur][tp][2], bf[cur][tp][3]);
                }
        }

        __syncthreads();                 // all warps done reading stage s
        if (kt + 2 < KITERS) issue(kt + 2, s);
        else                 CP_ASYNC_COMMIT();   // keep pending-count exact
        CP_ASYNC_WAIT1();                // tile kt+1 (stage s^1) landed
        __syncthreads();
        s ^= 1;
        if (kt + 1 < KITERS) {
            const uint32_t As2 = sbase + s * STAGE_BYTES;
            load_frags(As2, As2 + A_BYTES, 0, af[0], bf[0]);
        }
    }

    // --- epilogue: *(1/256) + bias, fp32 out ---
    const int q  = lane >> 2;        // 0..7
    const int cc = (lane & 3) * 2;

    float2 bv[8];
#pragma unroll
    for (int ni = 0; ni < 8; ni++) {
        int n = Ntile * BN + wn * 64 + ni * 8 + cc;
        bv[ni] = *reinterpret_cast<const float2*>(bias + n);
    }

#pragma unroll
    for (int mi = 0; mi < 4; mi++) {
        int m0 = Mtile * BM + wm * 64 + mi * 16 + q;
#pragma unroll
        for (int ni = 0; ni < 8; ni++) {
            int n = Ntile * BN + wn * 64 + ni * 8 + cc;
            float2 v0, v1;
            v0.x = acc[mi][ni][0] * INV_W_SCALE + bv[ni].x;
            v0.y = acc[mi][ni][1] * INV_W_SCALE + bv[ni].y;
            v1.x = acc[mi][ni][2] * INV_W_SCALE + bv[ni].x;
            v1.y = acc[mi][ni][3] * INV_W_SCALE + bv[ni].y;
            *reinterpret_cast<float2*>(out + (size_t)m0 * OUT_F + n) = v0;
            *reinterpret_cast<float2*>(out + (size_t)(m0 + 8) * OUT_F + n) = v1;
        }
    }
}

// ------------------------------ host launch -------------------------------

extern "C" void kernel_launch(void* const* d_in, const int* in_sizes, int n_in,
                              void* d_out, int out_size) {
    const float* x    = (const float*)d_in[0];
    const float* a    = (const float*)d_in[1];
    const float* s    = (const float*)d_in[2];
    const float* bias = (const float*)d_in[3];
    float* out = (float*)d_out;

    conv_x_kernel<<<(int)((size_t)TOKENS * IN_F / 4 / 256), 256>>>(x);
    build_w_kernel<<<(4u * 1024u * 1024u) / 256u, 256>>>(a, s);

    cudaFuncSetAttribute(gemm_kernel,
                         cudaFuncAttributeMaxDynamicSharedMemorySize,
                         SMEM_TOTAL);
    gemm_kernel<<<dim3(TOKENS / BM, OUT_F / BN, 1), 256, SMEM_TOTAL>>>(bias, out);
}

// round 7
// speedup vs baseline: 1.4235x; 1.1151x over previous
#include <cuda_runtime.h>
#include <cuda_fp16.h>
#include <cstdint>

// ===========================================================================
// QLinear: y[8192,4096] = x[8192,4096] @ w^T + bias,  w = sum_k kron(a_k,s_k)
//
// Model: fallback HMMA.16816.F32 rt=8 cyc/SMSP on sm_103 => 2048 cyc floor
// per 64-wide ktile. R5 hit 84% of floor; the gap is ktile-boundary clumping
// (cp.async burst + 2 syncs + exposed LDSM).
// R6: BK=64, 3 stages, ONE __syncthreads per ktile, cp.async issue spread
// across the 4 ks-steps (3 chunks/step) so LDGSTS interleaves with HMMA.
// Config: BM=128 BN=256 BK=64, 8 warps (2x4), warp tile 64x64, 144KB smem.
// ===========================================================================

static constexpr int TOKENS = 8192;
static constexpr int IN_F   = 4096;
static constexpr int OUT_F  = 4096;

static constexpr int BM = 128;
static constexpr int BN = 256;
static constexpr int BK = 64;                        // halfs; 128B rows
static constexpr int STAGES = 3;
static constexpr int KITERS = IN_F / BK;             // 64

static constexpr int ROWB = BK * 2;                  // 128 B per smem row
static constexpr int A_BYTES = BM * ROWB;            // 16 KB
static constexpr int B_BYTES = BN * ROWB;            // 32 KB
static constexpr int STAGE_BYTES = A_BYTES + B_BYTES;      // 48 KB
static constexpr int SMEM_TOTAL  = STAGES * STAGE_BYTES;   // 144 KB

static constexpr float W_SCALE     = 256.0f;
static constexpr float INV_W_SCALE = 1.0f / 256.0f;

__device__ __half g_xh[(size_t)TOKENS * IN_F];   // 64 MB scratch
__device__ __half g_wh[(size_t)OUT_F * IN_F];    // 32 MB scratch

#define DI static __device__ __forceinline__

DI uint32_t smem_u32(const void* p) {
    uint32_t a;
    asm("{ .reg .u64 t; cvta.to.shared.u64 t, %1; cvt.u32.u64 %0, t; }"
        : "=r"(a) : "l"(p));
    return a;
}

#define CP_ASYNC_16(dst, src) \
    asm volatile("cp.async.cg.shared.global [%0], [%1], 16;" \
        :: "r"(dst), "l"(src) : "memory")

#define CP_ASYNC_COMMIT() asm volatile("cp.async.commit_group;" ::: "memory")
#define CP_ASYNC_WAIT1()  asm volatile("cp.async.wait_group 1;" ::: "memory")

#define LDSM_X4(R0, R1, R2, R3, addr) \
    asm volatile("ldmatrix.sync.aligned.m8n8.x4.shared.b16 {%0,%1,%2,%3}, [%4];" \
        : "=r"(R0), "=r"(R1), "=r"(R2), "=r"(R3) : "r"(addr))

#define MMA16816(C, A0, A1, A2, A3, B0, B1) \
    asm volatile("mma.sync.aligned.m16n8k16.row.col.f32.f16.f16.f32 " \
        "{%0,%1,%2,%3}, {%4,%5,%6,%7}, {%8,%9}, {%0,%1,%2,%3};" \
        : "+f"((C)[0]), "+f"((C)[1]), "+f"((C)[2]), "+f"((C)[3]) \
        : "r"(A0), "r"(A1), "r"(A2), "r"(A3), "r"(B0), "r"(B1))

// ------------------------------ prep kernels ------------------------------

__global__ void conv_x_kernel(const float* __restrict__ x) {
    size_t t = (size_t)blockIdx.x * blockDim.x + threadIdx.x;
    float4 v = reinterpret_cast<const float4*>(x)[t];
    __half2* o = reinterpret_cast<__half2*>(g_xh);
    o[2 * t + 0] = __floats2half2_rn(v.x, v.y);
    o[2 * t + 1] = __floats2half2_rn(v.z, v.w);
}

__global__ void build_w_kernel(const float* __restrict__ a,
                               const float* __restrict__ s) {
    uint32_t t = blockIdx.x * blockDim.x + threadIdx.x;   // 4M threads
    uint32_t q = t & 1023u;
    uint32_t p = (t >> 10) & 1023u;
    uint32_t j = t >> 20;

    float s0 = s[0u * 1048576u + p * 1024u + q];
    float s1 = s[1u * 1048576u + p * 1024u + q];
    float s2 = s[2u * 1048576u + p * 1024u + q];
    float s3 = s[3u * 1048576u + p * 1024u + q];

#pragma unroll
    for (int i = 0; i < 4; i++) {
        float w = __ldg(&a[0 * 16 + i * 4 + j]) * s0
                + __ldg(&a[1 * 16 + i * 4 + j]) * s1
                + __ldg(&a[2 * 16 + i * 4 + j]) * s2
                + __ldg(&a[3 * 16 + i * 4 + j]) * s3;
        g_wh[(size_t)(i * 1024 + p) * IN_F + j * 1024 + q] =
            __float2half_rn(w * W_SCALE);
    }
}

// ------------------------------ GEMM kernel -------------------------------
// SMEM rows 128B (8 chunks of 16B); chunk c of row m stored at (c ^ (m&7)).
// One __syncthreads per ktile; cp.async for tile kt+2 spread over ks-steps.

__global__ __launch_bounds__(256, 1)
void gemm_kernel(const float* __restrict__ bias, float* __restrict__ out) {
    extern __shared__ char smem[];
    const uint32_t sbase = smem_u32(smem);

    const int tid  = threadIdx.x;
    const int lane = tid & 31;
    const int wid  = tid >> 5;
    const int wm   = wid & 1;     // warp row (2)
    const int wn   = wid >> 1;    // warp col (4)
    const int g    = lane >> 3;
    const int r    = lane & 7;

    const int Mtile = blockIdx.x;
    const int Ntile = blockIdx.y;

    const __half* gA = g_xh + (size_t)(Mtile * BM) * IN_F;
    const __half* gB = g_wh + (size_t)(Ntile * BN) * IN_F;

    // --- one 16B-chunk-slice of the fill for tile kt into stage st ---
    // i in 0..11: i<4 -> A slice, else B slice (i-4 in 0..7)
    auto issue_chunk = [&](int kt, int st, int i) {
        const uint32_t base = sbase + st * STAGE_BYTES;
        if (i < 4) {
            int idx = tid + i * 256;           // 0..1023
            int m = idx >> 3, c = idx & 7;
            uint32_t off = m * ROWB + ((c ^ (m & 7)) << 4);
            CP_ASYNC_16(base + off, gA + (size_t)m * IN_F + kt * BK + c * 8);
        } else {
            int idx = tid + (i - 4) * 256;     // 0..2047
            int n = idx >> 3, c = idx & 7;
            uint32_t off = n * ROWB + ((c ^ (n & 7)) << 4);
            CP_ASYNC_16(base + A_BYTES + off,
                        gB + (size_t)n * IN_F + kt * BK + c * 8);
        }
    };
    auto issue_full = [&](int kt, int st) {
#pragma unroll
        for (int i = 0; i < 12; i++) issue_chunk(kt, st, i);
        CP_ASYNC_COMMIT();
    };

    // --- per-lane ldmatrix row bases ---
    int rowA[4];
    const int cpA = g >> 1;
#pragma unroll
    for (int mi = 0; mi < 4; mi++)
        rowA[mi] = wm * 64 + mi * 16 + (g & 1) * 8 + r;
    int rowB[4];
    const int cpB = g & 1;
#pragma unroll
    for (int tp = 0; tp < 4; tp++)
        rowB[tp] = wn * 64 + tp * 16 + ((g >> 1) & 1) * 8 + r;

    // ks in 0..3 selects 32B (2-chunk) k-slice within the 128B row
    auto load_frags = [&](uint32_t As, uint32_t Bs, int ks,
                          uint32_t (&a)[4][4], uint32_t (&b)[4][4]) {
        const uint32_t chA = (uint32_t)(((2 * ks + cpA) ^ r) << 4);
        const uint32_t chB = (uint32_t)(((2 * ks + cpB) ^ r) << 4);
#pragma unroll
        for (int mi = 0; mi < 4; mi++)
            LDSM_X4(a[mi][0], a[mi][1], a[mi][2], a[mi][3],
                    As + rowA[mi] * ROWB + chA);
#pragma unroll
        for (int tp = 0; tp < 4; tp++)
            LDSM_X4(b[tp][0], b[tp][1], b[tp][2], b[tp][3],
                    Bs + rowB[tp] * ROWB + chB);
    };

    float acc[4][8][4];
#pragma unroll
    for (int mi = 0; mi < 4; mi++)
#pragma unroll
        for (int ni = 0; ni < 8; ni++)
#pragma unroll
            for (int e = 0; e < 4; e++) acc[mi][ni][e] = 0.0f;

    // --- prologue: tiles 0,1 into stages 0,1 ---
    issue_full(0, 0);
    issue_full(1, 1);
    CP_ASYNC_WAIT1();           // tile 0 landed
    __syncthreads();

    uint32_t af[2][4][4], bf[2][4][4];
    load_frags(sbase, sbase + A_BYTES, 0, af[0], bf[0]);

    // --- mainloop: one barrier per ktile, spread prefetch of kt+2 ---
    int s = 0, sP = 2;          // consume stage; prefetch stage for kt+2
    for (int kt = 0; kt < KITERS; kt++) {
        const uint32_t As = sbase + s * STAGE_BYTES;
        const uint32_t Bs = As + A_BYTES;
        const bool pf = (kt + 2 < KITERS);

#pragma unroll
        for (int ks = 0; ks < 4; ks++) {
            const int cur = ks & 1;
            if (ks < 3) load_frags(As, Bs, ks + 1, af[cur ^ 1], bf[cur ^ 1]);
            if (pf) {
                issue_chunk(kt + 2, sP, 3 * ks + 0);
                issue_chunk(kt + 2, sP, 3 * ks + 1);
                issue_chunk(kt + 2, sP, 3 * ks + 2);
            }
#pragma unroll
            for (int mi = 0; mi < 4; mi++)
#pragma unroll
                for (int tp = 0; tp < 4; tp++) {
                    MMA16816(acc[mi][tp * 2 + 0],
                             af[cur][mi][0], af[cur][mi][1],
                             af[cur][mi][2], af[cur][mi][3],
                             bf[cur][tp][0], bf[cur][tp][1]);
                    MMA16816(acc[mi][tp * 2 + 1],
                             af[cur][mi][0], af[cur][mi][1],
                             af[cur][mi][2], af[cur][mi][3],
                             bf[cur][tp][2], bf[cur][tp][3]);
                }
        }

        CP_ASYNC_COMMIT();      // one group per ktile (empty in the tail)
        CP_ASYNC_WAIT1();       // tile kt+1 (issued at kt-1) landed
        __syncthreads();        // all warps done reading stage s

        if (++s == STAGES) s = 0;
        if (++sP == STAGES) sP = 0;
        if (kt + 1 < KITERS) {
            const uint32_t As2 = sbase + s * STAGE_BYTES;
            load_frags(As2, As2 + A_BYTES, 0, af[0], bf[0]);
        }
    }

    // --- epilogue: *(1/256) + bias, fp32 out ---
    const int q  = lane >> 2;
    const int cc = (lane & 3) * 2;

    float2 bv[8];
#pragma unroll
    for (int ni = 0; ni < 8; ni++) {
        int n = Ntile * BN + wn * 64 + ni * 8 + cc;
        bv[ni] = *reinterpret_cast<const float2*>(bias + n);
    }

#pragma unroll
    for (int mi = 0; mi < 4; mi++) {
        int m0 = Mtile * BM + wm * 64 + mi * 16 + q;
#pragma unroll
        for (int ni = 0; ni < 8; ni++) {
            int n = Ntile * BN + wn * 64 + ni * 8 + cc;
            float2 v0, v1;
            v0.x = acc[mi][ni][0] * INV_W_SCALE + bv[ni].x;
            v0.y = acc[mi][ni][1] * INV_W_SCALE + bv[ni].y;
            v1.x = acc[mi][ni][2] * INV_W_SCALE + bv[ni].x;
            v1.y = acc[mi][ni][3] * INV_W_SCALE + bv[ni].y;
            *reinterpret_cast<float2*>(out + (size_t)m0 * OUT_F + n) = v0;
            *reinterpret_cast<float2*>(out + (size_t)(m0 + 8) * OUT_F + n) = v1;
        }
    }
}

// ------------------------------ host launch -------------------------------

extern "C" void kernel_launch(void* const* d_in, const int* in_sizes, int n_in,
                              void* d_out, int out_size) {
    const float* x    = (const float*)d_in[0];
    const float* a    = (const float*)d_in[1];
    const float* s    = (const float*)d_in[2];
    const float* bias = (const float*)d_in[3];
    float* out = (float*)d_out;

    // build_w first (order shuffle so ncu -s 5 may land on a different kernel)
    build_w_kernel<<<(4u * 1024u * 1024u) / 256u, 256>>>(a, s);
    conv_x_kernel<<<(int)((size_t)TOKENS * IN_F / 4 / 256), 256>>>(x);

    cudaFuncSetAttribute(gemm_kernel,
                         cudaFuncAttributeMaxDynamicSharedMemorySize,
                         SMEM_TOTAL);
    gemm_kernel<<<dim3(TOKENS / BM, OUT_F / BN, 1), 256, SMEM_TOTAL>>>(bias, out);
}